// round 7
// baseline (speedup 1.0000x reference)
#include <cuda_runtime.h>
#include <cuda_bf16.h>
#include <cstdint>

#define Tn 512
#define Bn 128
#define Hn 1024
#define Vn 256
#define En 512
#define SCAN_CTAS 128
#define HP 512               // packed pairs per row (Hn/2)

typedef __nv_bfloat16 bf16;

// ---------------- packed scratch: uint2 = {hi(k),hi(k+1) | lo(k),lo(k+1)} ----
__device__ uint2 g_h1p[(size_t)Tn * Bn * HP];
__device__ uint2 g_h2p[(size_t)Tn * Bn * HP];
__device__ uint2 g_nmp[(size_t)Tn * Bn * HP];
__device__ float g_xp1[(size_t)Tn * Bn * Hn];
__device__ float g_xpe[Vn * Hn];
__device__ uint2 g_wh0p[Hn * HP];
__device__ uint2 g_wh1p[Hn * HP];
__device__ uint2 g_wi1p[Hn * HP];
__device__ uint2 g_pwp [Vn * HP];

// grid-barrier state: monotonic counters, replay-safe
__device__ unsigned g_bar_cnt = 0;
__device__ unsigned g_bar_gen = 0;

// ---------------- helpers ---------------------------------------------------
__device__ __forceinline__ void mma_bf16(float* c,
    uint32_t a0, uint32_t a1, uint32_t a2, uint32_t a3,
    uint32_t b0, uint32_t b1)
{
    asm volatile(
        "mma.sync.aligned.m16n8k16.row.col.f32.bf16.bf16.f32 "
        "{%0,%1,%2,%3}, {%4,%5,%6,%7}, {%8,%9}, {%0,%1,%2,%3};\n"
        : "+f"(c[0]), "+f"(c[1]), "+f"(c[2]), "+f"(c[3])
        : "r"(a0), "r"(a1), "r"(a2), "r"(a3), "r"(b0), "r"(b1));
}

// ---------------- weight splitting into packed hi/lo ------------------------
__global__ void split_pack_kernel(const float* __restrict__ src,
                                  uint2* __restrict__ dst, int npairs)
{
    int p = blockIdx.x * 256 + threadIdx.x;
    if (p < npairs) {
        float v0 = src[2 * p], v1 = src[2 * p + 1];
        bf16 h0 = __float2bfloat16(v0);
        bf16 l0 = __float2bfloat16(v0 - __bfloat162float(h0));
        bf16 h1 = __float2bfloat16(v1);
        bf16 l1 = __float2bfloat16(v1 - __bfloat162float(h1));
        __nv_bfloat162 hi; hi.x = h0; hi.y = h1;
        __nv_bfloat162 lo; lo.x = l0; lo.y = l1;
        uint2 o;
        o.x = *reinterpret_cast<uint32_t*>(&hi);
        o.y = *reinterpret_cast<uint32_t*>(&lo);
        dst[p] = o;
    }
}

// ---------------- xpe[v][h] = Wi0 @ emb[v] + bi0 (fp32) ---------------------
__global__ void __launch_bounds__(256) xpe_kernel(
    const float* __restrict__ emb, const float* __restrict__ wi0,
    const float* __restrict__ bi0, float* __restrict__ xpe)
{
    __shared__ float se[16][33];
    __shared__ float sw[64][33];
    int vbase = blockIdx.x * 16, hbase = blockIdx.y * 64;
    int tid = threadIdx.x;
    int vl = tid >> 4;
    int hl = (tid & 15) * 4;
    float acc[4] = {0.f, 0.f, 0.f, 0.f};
    for (int k0 = 0; k0 < En; k0 += 32) {
        for (int i = tid; i < 16 * 32; i += 256)
            se[i >> 5][i & 31] = emb[(size_t)(vbase + (i >> 5)) * En + k0 + (i & 31)];
        for (int i = tid; i < 64 * 32; i += 256)
            sw[i >> 5][i & 31] = wi0[(size_t)(hbase + (i >> 5)) * En + k0 + (i & 31)];
        __syncthreads();
#pragma unroll
        for (int kk = 0; kk < 32; kk++) {
            float a = se[vl][kk];
            acc[0] += a * sw[hl + 0][kk];
            acc[1] += a * sw[hl + 1][kk];
            acc[2] += a * sw[hl + 2][kk];
            acc[3] += a * sw[hl + 3][kk];
        }
        __syncthreads();
    }
#pragma unroll
    for (int p = 0; p < 4; p++)
        xpe[(size_t)(vbase + vl) * Hn + hbase + hl + p] = acc[p] + bi0[hbase + hl + p];
}

// ---------------- persistent scan: A from global, W SMEM-resident -----------
// 128 CTAs (32 N-tiles x 4 M-tiles). Per step: each of 8 warps computes the
// full 32x32 tile over its own 128-wide K-slice, A fragments loaded straight
// from global (packed LDG.64 gives hi+lo together), W fragments from resident
// SMEM (packed LDS.64). 8-way K-reduce via SMEM. 3 block syncs per step total.
//
// SMEM: W 16 chunks x 32 rows x 34 uint2 = 139,264 B; reduce 8*1028 f32 = 32,896 B
#define SCAN_SMEM_BYTES (16 * 1088 * 8 + 8 * 1028 * 4)

__global__ void __launch_bounds__(256, 1) scan_reg_kernel(
    const uint2* __restrict__ Wp, uint2* __restrict__ hseq,
    const float* __restrict__ xp, const int* __restrict__ x, int layer)
{
    extern __shared__ uint2 sm2[];
    uint2* sW = sm2;                                     // 16*1088 uint2
    float* sRed = reinterpret_cast<float*>(sm2 + 16 * 1088);

    int tid = threadIdx.x, lane = tid & 31, warp = tid >> 5;
    int g = lane >> 2, tq = lane & 3;
    int mbase = blockIdx.y * 32, nbase = blockIdx.x * 32;

    // load W tile once: rows nbase..nbase+31, all K (packed)
    for (int i = tid; i < 8192; i += 256) {
        int r = i >> 8;               // 0..31
        int p = (i & 255) * 2;        // pair 0..510 (even)
        int ch = p >> 5, pp = p & 31;
        *reinterpret_cast<uint4*>(&sW[ch * 1088 + r * 34 + pp]) =
            *reinterpret_cast<const uint4*>(&Wp[(size_t)(nbase + r) * HP + p]);
    }
    __syncthreads();

    unsigned gen0 = 0;
    if (tid == 0) gen0 = *(volatile unsigned*)&g_bar_gen;

    int em = tid >> 3, en = (tid & 7) * 4;
    int eb = mbase + em, egc = nbase + en;

    for (int t = 0; t < Tn; t++) {
        // prefetch xp_t (independent of h)
        float4 xv;
        if (layer == 0) {
            int xi = x[(size_t)eb * Tn + t];
            xv = *reinterpret_cast<const float4*>(xp + (size_t)xi * Hn + egc);
        } else {
            xv = *reinterpret_cast<const float4*>(xp + ((size_t)t * Bn + eb) * Hn + egc);
        }

        float outv[4] = {0.f, 0.f, 0.f, 0.f};

        if (t > 0) {
            const uint2* hp = hseq + (size_t)(t - 1) * Bn * HP;
            float acc[2][4][4] = {};
            int rA = mbase + g;

#pragma unroll
            for (int kk = 0; kk < 8; kk++) {
                int pb = warp * 64 + kk * 8 + tq;
                uint2 a[2][4];
#pragma unroll
                for (int mt = 0; mt < 2; mt++) {
                    int r0 = rA + mt * 16;
                    a[mt][0] = hp[(size_t)r0 * HP + pb];
                    a[mt][1] = hp[(size_t)(r0 + 8) * HP + pb];
                    a[mt][2] = hp[(size_t)r0 * HP + pb + 4];
                    a[mt][3] = hp[(size_t)(r0 + 8) * HP + pb + 4];
                }
                int ch = warp * 2 + (kk >> 2);
                int wq = (kk & 3) * 8 + tq;
                const uint2* wch = sW + ch * 1088;
#pragma unroll
                for (int j = 0; j < 4; j++) {
                    uint2 b0 = wch[(j * 8 + g) * 34 + wq];
                    uint2 b1 = wch[(j * 8 + g) * 34 + wq + 4];
#pragma unroll
                    for (int mt = 0; mt < 2; mt++) {
                        mma_bf16(acc[mt][j], a[mt][0].x, a[mt][1].x, a[mt][2].x, a[mt][3].x, b0.x, b1.x);
                        mma_bf16(acc[mt][j], a[mt][0].x, a[mt][1].x, a[mt][2].x, a[mt][3].x, b0.y, b1.y);
                        mma_bf16(acc[mt][j], a[mt][0].y, a[mt][1].y, a[mt][2].y, a[mt][3].y, b0.x, b1.x);
                    }
                }
            }

            // K-partials -> SMEM, 8-way reduce
#pragma unroll
            for (int mt = 0; mt < 2; mt++)
#pragma unroll
                for (int j = 0; j < 4; j++) {
                    int r0 = mt * 16 + g, cc = j * 8 + 2 * tq;
                    *reinterpret_cast<float2*>(&sRed[warp * 1028 + r0 * 32 + cc]) =
                        make_float2(acc[mt][j][0], acc[mt][j][1]);
                    *reinterpret_cast<float2*>(&sRed[warp * 1028 + (r0 + 8) * 32 + cc]) =
                        make_float2(acc[mt][j][2], acc[mt][j][3]);
                }
            __syncthreads();
#pragma unroll
            for (int w = 0; w < 8; w++) {
                float4 p = *reinterpret_cast<const float4*>(&sRed[w * 1028 + em * 32 + en]);
                outv[0] += p.x; outv[1] += p.y; outv[2] += p.z; outv[3] += p.w;
            }
        }

        // epilogue: tanh(gemm + xp), split, packed store (one uint4)
        {
            float xa[4] = {xv.x, xv.y, xv.z, xv.w};
            bf16 hh[4], ll[4];
#pragma unroll
            for (int i = 0; i < 4; i++) {
                float v = tanhf(outv[i] + xa[i]);
                hh[i] = __float2bfloat16(v);
                ll[i] = __float2bfloat16(v - __bfloat162float(hh[i]));
            }
            union { uint4 q; __nv_bfloat162 h2[4]; } U;
            U.h2[0].x = hh[0]; U.h2[0].y = hh[1];
            U.h2[1].x = ll[0]; U.h2[1].y = ll[1];
            U.h2[2].x = hh[2]; U.h2[2].y = hh[3];
            U.h2[3].x = ll[2]; U.h2[3].y = ll[3];
            *reinterpret_cast<uint4*>(&hseq[((size_t)t * Bn + eb) * HP + (egc >> 1)]) = U.q;
        }

        // grid barrier (monotonic, volatile-load polling)
        __threadfence();
        __syncthreads();
        if (tid == 0) {
            unsigned target = gen0 + (unsigned)t + 1u;
            unsigned old = atomicAdd(&g_bar_cnt, 1u);
            if (old == target * (unsigned)SCAN_CTAS - 1u) {
                atomicExch(&g_bar_gen, target);
            } else {
                while (*(volatile unsigned*)&g_bar_gen - gen0 < (unsigned)t + 1u)
                    __nanosleep(32);
            }
        }
        __syncthreads();
    }
}

// ---------------- big parallel GEMM (packed split-bf16 x3) ------------------
// C[m,n] = A[m,:] . W[n,:] + bias[n]
// mode 0: out fp32 row-major N=1024 (xproj layer 2); mode 1: logits scatter
__global__ void __launch_bounds__(256) gemm_split_kernel(
    const uint2* __restrict__ Ap, const uint2* __restrict__ Wp,
    const float* __restrict__ bias, float* __restrict__ outf, int mode)
{
    __shared__ uint2 sA[64][34], sB[64][34];
    int tid = threadIdx.x, lane = tid & 31, warp = tid >> 5;
    int wm = warp & 3, wn = warp >> 2;
    int mbase = blockIdx.x * 64, nbase = blockIdx.y * 64;
    int g = lane >> 2, tq = lane & 3;
    float c[4][4] = {};

    for (int k0 = 0; k0 < HP; k0 += 32) {        // 32 pairs = 64 elems per chunk
#pragma unroll
        for (int i = 0; i < 4; i++) {
            int idx = tid + i * 256;              // 0..1023
            int r = idx >> 4, q = (idx & 15) * 2;
            *reinterpret_cast<uint4*>(&sA[r][q]) =
                *reinterpret_cast<const uint4*>(&Ap[(size_t)(mbase + r) * HP + k0 + q]);
            *reinterpret_cast<uint4*>(&sB[r][q]) =
                *reinterpret_cast<const uint4*>(&Wp[(size_t)(nbase + r) * HP + k0 + q]);
        }
        __syncthreads();
#pragma unroll
        for (int kki = 0; kki < 4; kki++) {
            int bp = kki * 8 + tq;
            int ar = wm * 16 + g;
            uint2 a0 = sA[ar][bp];
            uint2 a1 = sA[ar + 8][bp];
            uint2 a2 = sA[ar][bp + 4];
            uint2 a3 = sA[ar + 8][bp + 4];
#pragma unroll
            for (int j = 0; j < 4; j++) {
                int br = wn * 32 + j * 8 + g;
                uint2 b0 = sB[br][bp];
                uint2 b1 = sB[br][bp + 4];
                mma_bf16(c[j], a0.x, a1.x, a2.x, a3.x, b0.x, b1.x);
                mma_bf16(c[j], a0.x, a1.x, a2.x, a3.x, b0.y, b1.y);
                mma_bf16(c[j], a0.y, a1.y, a2.y, a3.y, b0.x, b1.x);
            }
        }
        __syncthreads();
    }

#pragma unroll
    for (int j = 0; j < 4; j++) {
#pragma unroll
        for (int rh = 0; rh < 2; rh++) {
            int m = mbase + wm * 16 + g + rh * 8;
            int n = nbase + wn * 32 + j * 8 + 2 * tq;
            float v0 = c[j][rh * 2 + 0] + bias[n];
            float v1 = c[j][rh * 2 + 1] + bias[n + 1];
            if (mode == 0) {
                outf[(size_t)m * Hn + n] = v0;
                outf[(size_t)m * Hn + n + 1] = v1;
            } else {
                int b = m & (Bn - 1), t = m >> 7;
                size_t o = ((size_t)b * Tn + t) * Vn + n;
                outf[o] = v0;
                outf[o + 1] = v1;
            }
        }
    }
}

// ---------------- layernorm (packed in/out) ----------------------------------
__global__ void __launch_bounds__(256) ln_kernel(
    const uint2* __restrict__ hp, const float* __restrict__ gam,
    const float* __restrict__ bet, uint2* __restrict__ nm)
{
    __shared__ float red[18];
    size_t row = blockIdx.x;
    int tid = threadIdx.x;
    int c0 = tid * 4;

    uint4 in = *reinterpret_cast<const uint4*>(&hp[row * HP + tid * 2]);
    const __nv_bfloat162* pcs = reinterpret_cast<const __nv_bfloat162*>(&in);
    float v[4];
    v[0] = __bfloat162float(pcs[0].x) + __bfloat162float(pcs[1].x);
    v[1] = __bfloat162float(pcs[0].y) + __bfloat162float(pcs[1].y);
    v[2] = __bfloat162float(pcs[2].x) + __bfloat162float(pcs[3].x);
    v[3] = __bfloat162float(pcs[2].y) + __bfloat162float(pcs[3].y);

    float s = 0.f, q = 0.f;
#pragma unroll
    for (int i = 0; i < 4; i++) { s += v[i]; q += v[i] * v[i]; }
#pragma unroll
    for (int o = 16; o; o >>= 1) {
        s += __shfl_xor_sync(0xffffffffu, s, o);
        q += __shfl_xor_sync(0xffffffffu, q, o);
    }
    int warp = tid >> 5, lane = tid & 31;
    if (lane == 0) { red[warp] = s; red[warp + 8] = q; }
    __syncthreads();
    if (tid == 0) {
        float ss = 0.f, qq = 0.f;
#pragma unroll
        for (int i = 0; i < 8; i++) { ss += red[i]; qq += red[i + 8]; }
        float mu = ss / (float)Hn;
        float var = qq / (float)Hn - mu * mu;
        red[16] = mu;
        red[17] = rsqrtf(var + 1e-5f);
    }
    __syncthreads();
    float mu = red[16], rstd = red[17];

    bf16 hh[4], ll[4];
#pragma unroll
    for (int i = 0; i < 4; i++) {
        float nv = (v[i] - mu) * rstd * gam[c0 + i] + bet[c0 + i];
        hh[i] = __float2bfloat16(nv);
        ll[i] = __float2bfloat16(nv - __bfloat162float(hh[i]));
    }
    union { uint4 q4; __nv_bfloat162 h2[4]; } U;
    U.h2[0].x = hh[0]; U.h2[0].y = hh[1];
    U.h2[1].x = ll[0]; U.h2[1].y = ll[1];
    U.h2[2].x = hh[2]; U.h2[2].y = hh[3];
    U.h2[3].x = ll[2]; U.h2[3].y = ll[3];
    *reinterpret_cast<uint4*>(&nm[row * HP + tid * 2]) = U.q4;
}

// ---------------- launch ------------------------------------------------------
extern "C" void kernel_launch(void* const* d_in, const int* in_sizes, int n_in,
                              void* d_out, int out_size)
{
    const float* emb    = (const float*)d_in[0];
    const float* wi0    = (const float*)d_in[1];
    const float* bi0    = (const float*)d_in[2];
    const float* wh0    = (const float*)d_in[3];
    const float* wi1    = (const float*)d_in[4];
    const float* bi1    = (const float*)d_in[5];
    const float* wh1    = (const float*)d_in[6];
    const float* ln_g   = (const float*)d_in[7];
    const float* ln_b   = (const float*)d_in[8];
    const float* proj_w = (const float*)d_in[9];
    const float* proj_b = (const float*)d_in[10];
    const int*   x      = (const int*)d_in[11];

    uint2 *h1p, *h2p, *nmp, *wh0p, *wh1p, *wi1p, *pwp;
    float *xp1, *xpe;
    cudaGetSymbolAddress((void**)&h1p,  g_h1p);
    cudaGetSymbolAddress((void**)&h2p,  g_h2p);
    cudaGetSymbolAddress((void**)&nmp,  g_nmp);
    cudaGetSymbolAddress((void**)&wh0p, g_wh0p);
    cudaGetSymbolAddress((void**)&wh1p, g_wh1p);
    cudaGetSymbolAddress((void**)&wi1p, g_wi1p);
    cudaGetSymbolAddress((void**)&pwp,  g_pwp);
    cudaGetSymbolAddress((void**)&xp1,  g_xp1);
    cudaGetSymbolAddress((void**)&xpe,  g_xpe);

    cudaFuncSetAttribute(scan_reg_kernel,
                         cudaFuncAttributeMaxDynamicSharedMemorySize,
                         SCAN_SMEM_BYTES);

    split_pack_kernel<<<(Hn * HP + 255) / 256, 256>>>(wh0, wh0p, Hn * HP);
    split_pack_kernel<<<(Hn * HP + 255) / 256, 256>>>(wh1, wh1p, Hn * HP);
    split_pack_kernel<<<(Hn * HP + 255) / 256, 256>>>(wi1, wi1p, Hn * HP);
    split_pack_kernel<<<(Vn * HP + 255) / 256, 256>>>(proj_w, pwp, Vn * HP);

    xpe_kernel<<<dim3(16, 16), 256>>>(emb, wi0, bi0, xpe);

    scan_reg_kernel<<<dim3(32, 4), 256, SCAN_SMEM_BYTES>>>(
        wh0p, h1p, xpe, x, 0);

    gemm_split_kernel<<<dim3(1024, 16), 256>>>(h1p, wi1p, bi1, xp1, 0);

    scan_reg_kernel<<<dim3(32, 4), 256, SCAN_SMEM_BYTES>>>(
        wh1p, h2p, xp1, x, 1);

    ln_kernel<<<Tn * Bn, 256>>>(h2p, ln_g, ln_b, nmp);

    gemm_split_kernel<<<dim3(1024, 4), 256>>>(nmp, pwp, proj_b, (float*)d_out, 1);
}